// round 16
// baseline (speedup 1.0000x reference)
#include <cuda_runtime.h>
#include <cuda_fp16.h>
#include <math.h>
#include <stdint.h>

// Problem constants
#define Bq 2
#define Lq 1024
#define Hq 1024
#define Dq 2048
#define Nq 16
#define Kq 4
#define Rq 64
#define Mq (Bq*Lq)          // 2048 rows
#define E2D (2*Dq)          // 4096
#define SSMW (Rq + 2*Nq)    // 96
#define NC 8                // scan chunks
#define CL (Lq/NC)          // 128 steps per chunk

// fp32 scratch (atomic accumulation targets only)
__device__ float g_ssm[(size_t)Mq * SSMW];

// chunked-scan state
__device__ float g_hend[(size_t)Bq * NC * Dq * Nq];
__device__ float g_hin [(size_t)Bq * NC * Dq * Nq];
__device__ float g_S   [(size_t)Bq * NC * Dq];

// fp16 intermediates
__device__ __half g_proj[(size_t)Mq * E2D];      // proj output (x | gate)
__device__ __half g_dt[(size_t)Mq * Dq];         // softplus(dt)
__device__ __half g_hid_h[(size_t)Mq * Hq];
__device__ __half g_win_h[(size_t)E2D * Hq];
__device__ __half g_x_h[(size_t)Mq * Dq];
__device__ __half g_wx_h[(size_t)128 * Dq];
__device__ __half g_dtlr_h[(size_t)Mq * Rq];
__device__ __half g_wdt_h[(size_t)Dq * Rq];
__device__ __half g_y_h[(size_t)Mq * Dq];
__device__ __half g_wout_h[(size_t)Hq * Dq];

__device__ __forceinline__ uint32_t smem_u32(const void* p) {
    uint32_t a;
    asm("{ .reg .u64 t; cvta.to.shared.u64 t, %1; cvt.u32.u64 %0, t; }"
        : "=r"(a) : "l"(p));
    return a;
}
#define SW128(x) ((x) ^ (((x) >> 3) & 0x70))

// ============================================================================
// fp32 -> fp16 single plane (supports ld != take)
// ============================================================================
__global__ void cvt_f16(const float* __restrict__ src,
                        __half* __restrict__ dst,
                        int rows, int ld, int take)
{
    int q = take >> 2;
    size_t idx = (size_t)blockIdx.x * blockDim.x + threadIdx.x;
    if (idx >= (size_t)rows * q) return;
    int row = (int)(idx / q);
    int c4 = (int)(idx % q) * 4;
    float4 v = *(const float4*)(src + (size_t)row * ld + c4);
    __half2* pd = (__half2*)(dst + (size_t)row * take + c4);
    pd[0] = __half2(__float2half_rn(v.x), __float2half_rn(v.y));
    pd[1] = __half2(__float2half_rn(v.z), __float2half_rn(v.w));
}

// ============================================================================
// Fused weight conversion: W_in, W_dt, W_x (zero-padded 96->128), W_out.
// ============================================================================
#define PW_N1 ((size_t)E2D * Hq / 4)
#define PW_N2 ((size_t)Dq * Rq / 4)
#define PW_N3 ((size_t)128 * Dq / 4)
#define PW_N4 ((size_t)Hq * Dq / 4)
#define PW_TOT (PW_N1 + PW_N2 + PW_N3 + PW_N4)

__device__ __forceinline__ void cvt4(const float* __restrict__ s,
                                     __half* __restrict__ d, size_t j)
{
    float4 v = ((const float4*)s)[j];
    __half2* pd = (__half2*)(d + j * 4);
    pd[0] = __half2(__float2half_rn(v.x), __float2half_rn(v.y));
    pd[1] = __half2(__float2half_rn(v.z), __float2half_rn(v.w));
}

__global__ void prep_weights(const float* __restrict__ W_in, __half* __restrict__ winh,
                             const float* __restrict__ W_dt, __half* __restrict__ wdth,
                             const float* __restrict__ W_x,  __half* __restrict__ wxh,
                             const float* __restrict__ W_out,__half* __restrict__ wouth)
{
    size_t i = (size_t)blockIdx.x * blockDim.x + threadIdx.x;
    if (i < PW_N1) { cvt4(W_in, winh, i); return; }
    i -= PW_N1;
    if (i < PW_N2) { cvt4(W_dt, wdth, i); return; }
    i -= PW_N2;
    if (i < PW_N3) {
        size_t e = i * 4;
        int row = (int)(e / Dq);
        __half2* pd = (__half2*)(wxh + e);
        if (row < SSMW) {
            float4 v = *(const float4*)(W_x + e);
            pd[0] = __half2(__float2half_rn(v.x), __float2half_rn(v.y));
            pd[1] = __half2(__float2half_rn(v.z), __float2half_rn(v.w));
        } else {
            pd[0] = __half2(__float2half_rn(0.f), __float2half_rn(0.f));
            pd[1] = pd[0];
        }
        return;
    }
    i -= PW_N3;
    if (i < PW_N4) cvt4(W_out, wouth, i);
}

// zero g_ssm and d_out in one kernel
#define Z_N1 ((size_t)Mq * SSMW / 4)
#define Z_N2 ((size_t)Mq * Hq / 4)
__global__ void zeros_kernel(float* __restrict__ ssm, float* __restrict__ outp)
{
    size_t i = (size_t)blockIdx.x * blockDim.x + threadIdx.x;
    float4 z = make_float4(0.f, 0.f, 0.f, 0.f);
    if (i < Z_N1) { ((float4*)ssm)[i] = z; return; }
    i -= Z_N1;
    if (i < Z_N2) ((float4*)outp)[i] = z;
}

// ============================================================================
// Tensor-core NT GEMM via mma.sync m16n8k16 fp16, single plane per operand.
// 128x128 CTA tile, BK=64 (SW128 smem), 3-stage cp.async pipeline.
// Output: kz>1 -> fp32 atomicAdd into C (pre-zeroed);
//         kz==1 && Ch -> fp16 stores into Ch; else fp32 stores into C.
// mode 1: softplus(acc + bias[n]).  nmax clips output columns.
// ============================================================================
#define TCM 128
#define TCN 128
#define TCK 64
#define TILE_B 16384
#define BUF_B (2*TILE_B)
#define NSTAGE 3
#define SMEM_TC_TOTAL (NSTAGE*BUF_B)

#define LDMX4(r0,r1,r2,r3,addr) \
    asm volatile("ldmatrix.sync.aligned.m8n8.x4.shared.b16 {%0,%1,%2,%3}, [%4];" \
        : "=r"(r0), "=r"(r1), "=r"(r2), "=r"(r3) : "r"(addr))

#define MMAF16(d, a, b) \
    asm volatile("mma.sync.aligned.m16n8k16.row.col.f32.f16.f16.f32 " \
        "{%0,%1,%2,%3}, {%4,%5,%6,%7}, {%8,%9}, {%0,%1,%2,%3};" \
        : "+f"((d)[0]), "+f"((d)[1]), "+f"((d)[2]), "+f"((d)[3]) \
        : "r"((a)[0]), "r"((a)[1]), "r"((a)[2]), "r"((a)[3]), \
          "r"((b)[0]), "r"((b)[1]))

__global__ void __launch_bounds__(256, 2)
gemm_tc(const __half* __restrict__ Ah, const __half* __restrict__ Bh,
        float* __restrict__ C, __half* __restrict__ Ch,
        int K, int lda, int ldb, int ldc,
        const float* __restrict__ bias, int mode, int nmax)
{
    extern __shared__ char smem[];
    const uint32_t sb = smem_u32(smem);
    const int tid = threadIdx.x;
    const int wid = tid >> 5;
    const int lid = tid & 31;
    const int warp_m = wid & 3;
    const int warp_n = wid >> 2;
    const int m0 = blockIdx.y * TCM;
    const int n0 = blockIdx.x * TCN;
    const int kz = gridDim.z;
    const int KT = K / TCK / kz;
    const int kt0 = blockIdx.z * KT;

    const __half* planes[2] = {Ah, Bh};
    const int plds[2] = {lda, ldb};
    const int pbase[2] = {m0, n0};

    auto issue_tile = [&](int j) {
        if (j < KT) {
            int kofs = (kt0 + j) * TCK;
            uint32_t dbase = sb + (j % NSTAGE) * BUF_B;
            #pragma unroll
            for (int t = 0; t < 8; t++) {
                int idx = t * 256 + tid;
                int p = idx >> 10;
                int rem = idx & 1023;
                int row = rem >> 3;
                int c = rem & 7;
                const __half* src = planes[p]
                    + (size_t)(pbase[p] + row) * plds[p] + kofs + c * 8;
                uint32_t dst = dbase + p * TILE_B + SW128((uint32_t)row * 128 + c * 16);
                asm volatile("cp.async.cg.shared.global [%0], [%1], 16;"
                             :: "r"(dst), "l"(src) : "memory");
            }
        }
        asm volatile("cp.async.commit_group;" ::: "memory");
    };

    float acc[2][8][4];
    #pragma unroll
    for (int i = 0; i < 2; i++)
        #pragma unroll
        for (int j = 0; j < 8; j++)
            #pragma unroll
            for (int q = 0; q < 4; q++) acc[i][j][q] = 0.f;

    issue_tile(0);
    issue_tile(1);

    const int a_r = (lid & 7) + ((lid & 8) ? 8 : 0);
    const int a_kh = (lid & 16) ? 8 : 0;
    const int b_r = (lid & 7) + ((lid & 16) ? 8 : 0);
    const int b_kh = (lid & 8) ? 8 : 0;

    for (int kt = 0; kt < KT; kt++) {
        asm volatile("cp.async.wait_group 1;" ::: "memory");
        __syncthreads();
        issue_tile(kt + 2);

        uint32_t buf = sb + (kt % NSTAGE) * BUF_B;
        #pragma unroll
        for (int k16 = 0; k16 < 4; k16++) {
            uint32_t af[2][4];
            uint32_t bf[8][2];
            #pragma unroll
            for (int im = 0; im < 2; im++) {
                int row = warp_m * 32 + im * 16 + a_r;
                int kb = (k16 * 16 + a_kh) * 2;
                uint32_t ad = buf + SW128((uint32_t)row * 128 + kb);
                LDMX4(af[im][0], af[im][1], af[im][2], af[im][3], ad);
            }
            #pragma unroll
            for (int g = 0; g < 4; g++) {
                int row = warp_n * 64 + g * 16 + b_r;
                int kb = (k16 * 16 + b_kh) * 2;
                uint32_t bd = buf + TILE_B + SW128((uint32_t)row * 128 + kb);
                LDMX4(bf[g*2][0], bf[g*2][1], bf[g*2+1][0], bf[g*2+1][1], bd);
            }
            #pragma unroll
            for (int im = 0; im < 2; im++) {
                #pragma unroll
                for (int in = 0; in < 8; in++) {
                    MMAF16(acc[im][in], af[im], bf[in]);
                }
            }
        }
    }

    const int rbase = m0 + warp_m * 32 + (lid >> 2);
    const int cbase = n0 + warp_n * 64 + (lid & 3) * 2;
    #pragma unroll
    for (int im = 0; im < 2; im++) {
        #pragma unroll
        for (int in = 0; in < 8; in++) {
            int c = cbase + in * 8;
            if (c >= nmax) continue;
            float v0 = acc[im][in][0], v1 = acc[im][in][1];
            float v2 = acc[im][in][2], v3 = acc[im][in][3];
            if (mode == 1) {
                float b0 = bias[c], b1 = bias[c + 1];
                v0 += b0; v1 += b1; v2 += b0; v3 += b1;
                v0 = (v0 > 20.f) ? v0 : log1pf(expf(v0));
                v1 = (v1 > 20.f) ? v1 : log1pf(expf(v1));
                v2 = (v2 > 20.f) ? v2 : log1pf(expf(v2));
                v3 = (v3 > 20.f) ? v3 : log1pf(expf(v3));
            }
            int r0 = rbase + im * 16;
            if (kz > 1) {
                atomicAdd(&C[(size_t)r0 * ldc + c],           v0);
                atomicAdd(&C[(size_t)r0 * ldc + c + 1],       v1);
                atomicAdd(&C[(size_t)(r0 + 8) * ldc + c],     v2);
                atomicAdd(&C[(size_t)(r0 + 8) * ldc + c + 1], v3);
            } else if (Ch) {
                *(__half2*)(Ch + (size_t)r0 * ldc + c) =
                    __half2(__float2half_rn(v0), __float2half_rn(v1));
                *(__half2*)(Ch + (size_t)(r0 + 8) * ldc + c) =
                    __half2(__float2half_rn(v2), __float2half_rn(v3));
            } else {
                *(float2*)(C + (size_t)r0 * ldc + c)       = make_float2(v0, v1);
                *(float2*)(C + (size_t)(r0 + 8) * ldc + c) = make_float2(v2, v3);
            }
        }
    }
}

// ---------------------------------------------------------------------------
// Causal depthwise conv (K=4) + bias + SiLU, fp16 in (proj) -> fp16 x.
// ---------------------------------------------------------------------------
__global__ void conv_silu_kernel(const __half* __restrict__ proj,
                                 const float* __restrict__ conv_w,
                                 const float* __restrict__ conv_b,
                                 __half* __restrict__ xh)
{
    size_t idx = (size_t)blockIdx.x * blockDim.x + threadIdx.x;
    if (idx >= (size_t)Mq * Dq) return;
    int d = (int)(idx % Dq);
    int l = (int)((idx / Dq) % Lq);
    int b = (int)(idx / ((size_t)Dq * Lq));

    const __half* pb = proj + (size_t)b * Lq * E2D + d;
    float acc = conv_b[d];
    #pragma unroll
    for (int k = 0; k < Kq; k++) {
        int li = l - (Kq - 1) + k;
        if (li >= 0)
            acc = fmaf(__half2float(pb[(size_t)li * E2D]), conv_w[d * Kq + k], acc);
    }
    float xv = acc / (1.f + __expf(-acc));
    xh[idx] = __float2half_rn(xv);
}

// ---------------------------------------------------------------------------
// Chunked SSM scan (two-pass, exact by linearity). NC=8 chunks of 128.
// dt/x/gate fp16; B/C fp32 (from atomic ssm buffer).
// ---------------------------------------------------------------------------
__device__ __forceinline__ void scan_negA(const float* A_log, int d, int nbase,
                                          float& a0, float& a1, float& a2, float& a3,
                                          bool& fast)
{
    a0 = -__expf(A_log[d * Nq + nbase + 0]);
    a1 = -__expf(A_log[d * Nq + nbase + 1]);
    a2 = -__expf(A_log[d * Nq + nbase + 2]);
    a3 = -__expf(A_log[d * Nq + nbase + 3]);
    fast = (fabsf(a0 + (float)(nbase + 1)) < 1e-3f * (nbase + 1))
        && (fabsf(a1 + (float)(nbase + 2)) < 1e-3f * (nbase + 2))
        && (fabsf(a2 + (float)(nbase + 3)) < 1e-3f * (nbase + 3))
        && (fabsf(a3 + (float)(nbase + 4)) < 1e-3f * (nbase + 4));
}

__global__ void __launch_bounds__(128)
scan_pass1(const float* __restrict__ ssm,
           const __half* __restrict__ dt,
           const __half* __restrict__ x,
           const float* __restrict__ A_log,
           float* __restrict__ hend,
           float* __restrict__ Ssum)
{
    const int quarter = threadIdx.x & 3;
    const int dl = threadIdx.x >> 2;
    const int d = blockIdx.x * 32 + dl;
    const int b = blockIdx.y;
    const int c = blockIdx.z;
    const int nbase = quarter * 4;
    const int l0 = c * CL;

    float negA0, negA1, negA2, negA3; bool fast;
    scan_negA(A_log, d, nbase, negA0, negA1, negA2, negA3, fast);

    const float*  ssm_b = ssm + (size_t)b * Lq * SSMW;
    const __half* dt_b  = dt  + (size_t)b * Lq * Dq + d;
    const __half* x_b   = x   + (size_t)b * Lq * Dq + d;

    float h0 = 0.f, h1 = 0.f, h2 = 0.f, h3 = 0.f;
    float S = 0.f;

    float pdt[2], px[2];
    float4 pB[2];
    #pragma unroll
    for (int s = 0; s < 2; s++) {
        pdt[s] = __half2float(dt_b[(size_t)(l0 + s) * Dq]);
        px[s]  = __half2float(x_b[(size_t)(l0 + s) * Dq]);
        pB[s]  = *(const float4*)(ssm_b + (size_t)(l0 + s) * SSMW + Rq + nbase);
    }

    for (int i = 0; i < CL; i++) {
        const int s = i & 1;
        float cdt = pdt[s], cx = px[s];
        float4 cB = pB[s];
        if (i + 2 < CL) {
            pdt[s] = __half2float(dt_b[(size_t)(l0 + i + 2) * Dq]);
            px[s]  = __half2float(x_b[(size_t)(l0 + i + 2) * Dq]);
            pB[s]  = *(const float4*)(ssm_b + (size_t)(l0 + i + 2) * SSMW + Rq + nbase);
        }

        float r0, r1, r2, r3;
        if (fast) {
            float q = __expf(-cdt);
            float q2 = q * q;
            float q4 = q2 * q2;
            r0 = q;
            if (quarter & 1) r0 *= q4;
            if (quarter & 2) r0 *= q4 * q4;
            r1 = r0 * q; r2 = r1 * q; r3 = r2 * q;
        } else {
            r0 = __expf(cdt * negA0);
            r1 = __expf(cdt * negA1);
            r2 = __expf(cdt * negA2);
            r3 = __expf(cdt * negA3);
        }

        S += cdt;
        float k = cdt * cx;
        h0 = fmaf(r0, h0, k * cB.x);
        h1 = fmaf(r1, h1, k * cB.y);
        h2 = fmaf(r2, h2, k * cB.z);
        h3 = fmaf(r3, h3, k * cB.w);
    }

    size_t hidx = ((((size_t)b * NC + c) * Dq) + d) * Nq + nbase;
    *(float4*)(hend + hidx) = make_float4(h0, h1, h2, h3);
    if (quarter == 0)
        Ssum[((size_t)b * NC + c) * Dq + d] = S;
}

__global__ void __launch_bounds__(128)
scan_combine(const float* __restrict__ hend,
             const float* __restrict__ Ssum,
             const float* __restrict__ A_log,
             float* __restrict__ hin)
{
    const int quarter = threadIdx.x & 3;
    const int dl = threadIdx.x >> 2;
    const int d = blockIdx.x * 32 + dl;
    const int b = blockIdx.y;
    const int nbase = quarter * 4;

    float negA0, negA1, negA2, negA3; bool fast;
    scan_negA(A_log, d, nbase, negA0, negA1, negA2, negA3, fast);
    (void)fast;

    float4 h = make_float4(0.f, 0.f, 0.f, 0.f);
    size_t base = (((size_t)b * NC) * Dq + d) * Nq + nbase;
    size_t stride = (size_t)Dq * Nq;

    *(float4*)(hin + base) = h;
    for (int c = 1; c < NC; c++) {
        float S = Ssum[((size_t)b * NC + c - 1) * Dq + d];
        float4 he = *(const float4*)(hend + base + (size_t)(c - 1) * stride);
        float p0 = __expf(negA0 * S);
        float p1 = __expf(negA1 * S);
        float p2 = __expf(negA2 * S);
        float p3 = __expf(negA3 * S);
        h.x = fmaf(p0, h.x, he.x);
        h.y = fmaf(p1, h.y, he.y);
        h.z = fmaf(p2, h.z, he.z);
        h.w = fmaf(p3, h.w, he.w);
        *(float4*)(hin + base + (size_t)c * stride) = h;
    }
}

__global__ void __launch_bounds__(128)
scan_pass2(const float* __restrict__ ssm,
           const __half* __restrict__ dt,
           const __half* __restrict__ x,
           const __half* __restrict__ proj,
           const float* __restrict__ A_log,
           const float* __restrict__ D_param,
           const float* __restrict__ hin,
           __half* __restrict__ yh)
{
    const int quarter = threadIdx.x & 3;
    const int dl = threadIdx.x >> 2;
    const int d = blockIdx.x * 32 + dl;
    const int b = blockIdx.y;
    const int c = blockIdx.z;
    const int nbase = quarter * 4;
    const int l0 = c * CL;

    float negA0, negA1, negA2, negA3; bool fast;
    scan_negA(A_log, d, nbase, negA0, negA1, negA2, negA3, fast);
    const float Dp = D_param[d];

    const float*  ssm_b = ssm  + (size_t)b * Lq * SSMW;
    const __half* dt_b  = dt   + (size_t)b * Lq * Dq + d;
    const __half* x_b   = x    + (size_t)b * Lq * Dq + d;
    const __half* g_bp  = proj + (size_t)b * Lq * E2D + Dq + d;
    __half* yh_b = yh + (size_t)b * Lq * Dq + d;

    float4 h4 = *(const float4*)(hin + ((((size_t)b * NC + c) * Dq) + d) * Nq + nbase);
    float h0 = h4.x, h1 = h4.y, h2 = h4.z, h3 = h4.w;

    float pdt[2], px[2], pg[2];
    float4 pB[2], pC[2];
    #pragma unroll
    for (int s = 0; s < 2; s++) {
        pdt[s] = __half2float(dt_b[(size_t)(l0 + s) * Dq]);
        px[s]  = __half2float(x_b[(size_t)(l0 + s) * Dq]);
        pg[s]  = __half2float(g_bp[(size_t)(l0 + s) * E2D]);
        pB[s]  = *(const float4*)(ssm_b + (size_t)(l0 + s) * SSMW + Rq + nbase);
        pC[s]  = *(const float4*)(ssm_b + (size_t)(l0 + s) * SSMW + Rq + Nq + nbase);
    }

    for (int i = 0; i < CL; i++) {
        const int s = i & 1;
        float cdt = pdt[s], cx = px[s], cg = pg[s];
        float4 cB = pB[s], cC = pC[s];
        if (i + 2 < CL) {
            pdt[s] = __half2float(dt_b[(size_t)(l0 + i + 2) * Dq]);
            px[s]  = __half2float(x_b[(size_t)(l0 + i + 2) * Dq]);
            pg[s]  = __half2float(g_bp[(size_t)(l0 + i + 2) * E2D]);
            pB[s]  = *(const float4*)(ssm_b + (size_t)(l0 + i + 2) * SSMW + Rq + nbase);
            pC[s]  = *(const float4*)(ssm_b + (size_t)(l0 + i + 2) * SSMW + Rq + Nq + nbase);
        }

        float r0, r1, r2, r3;
        if (fast) {
            float q = __expf(-cdt);
            float q2 = q * q;
            float q4 = q2 * q2;
            r0 = q;
            if (quarter & 1) r0 *= q4;
            if (quarter & 2) r0 *= q4 * q4;
            r1 = r0 * q; r2 = r1 * q; r3 = r2 * q;
        } else {
            r0 = __expf(cdt * negA0);
            r1 = __expf(cdt * negA1);
            r2 = __expf(cdt * negA2);
            r3 = __expf(cdt * negA3);
        }

        float k = cdt * cx;
        h0 = fmaf(r0, h0, k * cB.x);
        h1 = fmaf(r1, h1, k * cB.y);
        h2 = fmaf(r2, h2, k * cB.z);
        h3 = fmaf(r3, h3, k * cB.w);

        float cacc = fmaf(h0, cC.x, fmaf(h1, cC.y, fmaf(h2, cC.z, h3 * cC.w)));
        cacc += __shfl_xor_sync(0xffffffffu, cacc, 1, 4);
        cacc += __shfl_xor_sync(0xffffffffu, cacc, 2, 4);

        if (quarter == 0) {
            float sg = cg / (1.f + __expf(-cg));
            float yv = (cacc + cx * Dp) * sg;
            yh_b[(size_t)(l0 + i) * Dq] = __float2half_rn(yv);
        }
    }
}

// ---------------------------------------------------------------------------
extern "C" void kernel_launch(void* const* d_in, const int* in_sizes, int n_in,
                              void* d_out, int out_size)
{
    const float* hidden = (const float*)d_in[0];
    const float* W_in   = (const float*)d_in[1];
    const float* conv_w = (const float*)d_in[2];
    const float* conv_b = (const float*)d_in[3];
    const float* W_x    = (const float*)d_in[4];
    const float* W_dt   = (const float*)d_in[5];
    const float* b_dt   = (const float*)d_in[6];
    const float* A_log  = (const float*)d_in[7];
    const float* Dparam = (const float*)d_in[8];
    const float* W_out  = (const float*)d_in[9];
    float* out = (float*)d_out;

    float *ssm, *hend, *hin, *Ssum;
    cudaGetSymbolAddress((void**)&ssm, g_ssm);
    cudaGetSymbolAddress((void**)&hend, g_hend);
    cudaGetSymbolAddress((void**)&hin, g_hin);
    cudaGetSymbolAddress((void**)&Ssum, g_S);

    __half *projh, *dth, *hidh, *winh, *xh, *wxh, *dtlrh, *wdth, *yh, *wouth;
    cudaGetSymbolAddress((void**)&projh, g_proj);
    cudaGetSymbolAddress((void**)&dth, g_dt);
    cudaGetSymbolAddress((void**)&hidh, g_hid_h);
    cudaGetSymbolAddress((void**)&winh, g_win_h);
    cudaGetSymbolAddress((void**)&xh, g_x_h);
    cudaGetSymbolAddress((void**)&wxh, g_wx_h);
    cudaGetSymbolAddress((void**)&dtlrh, g_dtlr_h);
    cudaGetSymbolAddress((void**)&wdth, g_wdt_h);
    cudaGetSymbolAddress((void**)&yh, g_y_h);
    cudaGetSymbolAddress((void**)&wouth, g_wout_h);

    cudaFuncSetAttribute(gemm_tc, cudaFuncAttributeMaxDynamicSharedMemorySize,
                         SMEM_TC_TOTAL);

    auto nblk = [](size_t n) { return (unsigned)((n + 255) / 256); };

    // launch 0: hidden -> fp16
    cvt_f16<<<nblk((size_t)Mq * Hq / 4), 256>>>(hidden, hidh, Mq, Hq, Hq);
    // launch 1: all weight conversions fused
    prep_weights<<<nblk(PW_TOT), 256>>>(W_in, winh, W_dt, wdth, W_x, wxh,
                                        W_out, wouth);
    // launch 2: zero atomic-accumulated outputs (ssm, d_out)
    zeros_kernel<<<nblk(Z_N1 + Z_N2), 256>>>(ssm, out);

    // launch 3 (profiled): proj = hidden @ W_in^T -> fp16
    {
        dim3 grid(E2D / TCN, Mq / TCM, 1);
        gemm_tc<<<grid, 256, SMEM_TC_TOTAL>>>(hidh, winh, nullptr, projh,
                                              Hq, Hq, Hq, E2D, nullptr, 0, E2D);
    }

    // conv + silu -> x fp16
    conv_silu_kernel<<<nblk((size_t)Mq * Dq), 256>>>(projh, conv_w, conv_b, xh);

    // ssm_p = x @ W_x^T : (2048, 96), split-K=4 atomic (fp32)
    {
        dim3 grid(1, Mq / TCM, 4);
        gemm_tc<<<grid, 256, SMEM_TC_TOTAL>>>(xh, wxh, ssm, nullptr,
                                              Dq, Dq, Dq, SSMW, nullptr, 0, SSMW);
    }

    // dt = softplus(dt_lr @ W_dt^T + b_dt) -> fp16
    cvt_f16<<<nblk((size_t)Mq * Rq / 4), 256>>>(ssm, dtlrh, Mq, SSMW, Rq);
    {
        dim3 grid(Dq / TCN, Mq / TCM, 1);
        gemm_tc<<<grid, 256, SMEM_TC_TOTAL>>>(dtlrh, wdth, nullptr, dth,
                                              Rq, Rq, Rq, Dq, b_dt, 1, Dq);
    }

    // chunked scan: pass1 -> combine -> pass2 (y fp16)
    {
        dim3 g1(Dq / 32, Bq, NC);
        scan_pass1<<<g1, 128>>>(ssm, dth, xh, A_log, hend, Ssum);
        dim3 g2(Dq / 32, Bq);
        scan_combine<<<g2, 128>>>(hend, Ssum, A_log, hin);
        scan_pass2<<<g1, 128>>>(ssm, dth, xh, projh, A_log, Dparam, hin, yh);
    }

    // out = y @ W_out^T : (2048, 1024), split-K=2 atomic into d_out (fp32)
    {
        dim3 grid(Hq / TCN, Mq / TCM, 2);
        gemm_tc<<<grid, 256, SMEM_TC_TOTAL>>>(yh, wouth, out, nullptr,
                                              Dq, Dq, Dq, Hq, nullptr, 0, Hq);
    }
}

// round 17
// speedup vs baseline: 1.0409x; 1.0409x over previous
#include <cuda_runtime.h>
#include <cuda_fp16.h>
#include <math.h>
#include <stdint.h>

// Problem constants
#define Bq 2
#define Lq 1024
#define Hq 1024
#define Dq 2048
#define Nq 16
#define Kq 4
#define Rq 64
#define Mq (Bq*Lq)          // 2048 rows
#define E2D (2*Dq)          // 4096
#define SSMW (Rq + 2*Nq)    // 96
#define NC 8                // scan chunks
#define CL (Lq/NC)          // 128 steps per chunk

// fp32 scratch
__device__ float g_proj[(size_t)Mq * E2D];
__device__ float g_x[(size_t)Mq * Dq];
__device__ float g_ssm[(size_t)Mq * SSMW];
__device__ float g_dt[(size_t)Mq * Dq];

// chunked-scan state
__device__ float g_hend[(size_t)Bq * NC * Dq * Nq];
__device__ float g_S   [(size_t)Bq * NC * Dq];

// fp16 planes (single plane per operand)
__device__ __half g_hid_h[(size_t)Mq * Hq];
__device__ __half g_win_h[(size_t)E2D * Hq];
__device__ __half g_x_h[(size_t)Mq * Dq];
__device__ __half g_wx_h[(size_t)128 * Dq];
__device__ __half g_dtlr_h[(size_t)Mq * Rq];
__device__ __half g_wdt_h[(size_t)Dq * Rq];
__device__ __half g_y_h[(size_t)Mq * Dq];
__device__ __half g_wout_h[(size_t)Hq * Dq];

__device__ __forceinline__ uint32_t smem_u32(const void* p) {
    uint32_t a;
    asm("{ .reg .u64 t; cvta.to.shared.u64 t, %1; cvt.u32.u64 %0, t; }"
        : "=r"(a) : "l"(p));
    return a;
}
#define SW128(x) ((x) ^ (((x) >> 3) & 0x70))

// ============================================================================
// fp32 -> fp16 single plane (supports ld != take)
// ============================================================================
__global__ void cvt_f16(const float* __restrict__ src,
                        __half* __restrict__ dst,
                        int rows, int ld, int take)
{
    int q = take >> 2;
    size_t idx = (size_t)blockIdx.x * blockDim.x + threadIdx.x;
    if (idx >= (size_t)rows * q) return;
    int row = (int)(idx / q);
    int c4 = (int)(idx % q) * 4;
    float4 v = *(const float4*)(src + (size_t)row * ld + c4);
    __half2* pd = (__half2*)(dst + (size_t)row * take + c4);
    pd[0] = __half2(__float2half_rn(v.x), __float2half_rn(v.y));
    pd[1] = __half2(__float2half_rn(v.z), __float2half_rn(v.w));
}

// ============================================================================
// Fused weight conversion: W_in, W_dt, W_x (zero-padded 96->128), W_out.
// ============================================================================
#define PW_N1 ((size_t)E2D * Hq / 4)
#define PW_N2 ((size_t)Dq * Rq / 4)
#define PW_N3 ((size_t)128 * Dq / 4)
#define PW_N4 ((size_t)Hq * Dq / 4)
#define PW_TOT (PW_N1 + PW_N2 + PW_N3 + PW_N4)

__device__ __forceinline__ void cvt4(const float* __restrict__ s,
                                     __half* __restrict__ d, size_t j)
{
    float4 v = ((const float4*)s)[j];
    __half2* pd = (__half2*)(d + j * 4);
    pd[0] = __half2(__float2half_rn(v.x), __float2half_rn(v.y));
    pd[1] = __half2(__float2half_rn(v.z), __float2half_rn(v.w));
}

__global__ void prep_weights(const float* __restrict__ W_in, __half* __restrict__ winh,
                             const float* __restrict__ W_dt, __half* __restrict__ wdth,
                             const float* __restrict__ W_x,  __half* __restrict__ wxh,
                             const float* __restrict__ W_out,__half* __restrict__ wouth)
{
    size_t i = (size_t)blockIdx.x * blockDim.x + threadIdx.x;
    if (i < PW_N1) { cvt4(W_in, winh, i); return; }
    i -= PW_N1;
    if (i < PW_N2) { cvt4(W_dt, wdth, i); return; }
    i -= PW_N2;
    if (i < PW_N3) {
        size_t e = i * 4;
        int row = (int)(e / Dq);
        __half2* pd = (__half2*)(wxh + e);
        if (row < SSMW) {
            float4 v = *(const float4*)(W_x + e);
            pd[0] = __half2(__float2half_rn(v.x), __float2half_rn(v.y));
            pd[1] = __half2(__float2half_rn(v.z), __float2half_rn(v.w));
        } else {
            pd[0] = __half2(__float2half_rn(0.f), __float2half_rn(0.f));
            pd[1] = pd[0];
        }
        return;
    }
    i -= PW_N3;
    if (i < PW_N4) cvt4(W_out, wouth, i);
}

// zero g_ssm and d_out in one kernel
#define Z_N1 ((size_t)Mq * SSMW / 4)
#define Z_N2 ((size_t)Mq * Hq / 4)
__global__ void zeros_kernel(float* __restrict__ ssm, float* __restrict__ outp)
{
    size_t i = (size_t)blockIdx.x * blockDim.x + threadIdx.x;
    float4 z = make_float4(0.f, 0.f, 0.f, 0.f);
    if (i < Z_N1) { ((float4*)ssm)[i] = z; return; }
    i -= Z_N1;
    if (i < Z_N2) ((float4*)outp)[i] = z;
}

// ============================================================================
// Tensor-core NT GEMM via mma.sync m16n8k16 fp16, single plane per operand.
// 128x128 CTA tile, BK=64 (SW128 smem), 3-stage cp.async pipeline.
// Optional split-K via gridDim.z (atomicAdd, C pre-zeroed). nmax clips cols.
// ============================================================================
#define TCM 128
#define TCN 128
#define TCK 64
#define TILE_B 16384
#define BUF_B (2*TILE_B)
#define NSTAGE 3
#define SMEM_TC_TOTAL (NSTAGE*BUF_B)

#define LDMX4(r0,r1,r2,r3,addr) \
    asm volatile("ldmatrix.sync.aligned.m8n8.x4.shared.b16 {%0,%1,%2,%3}, [%4];" \
        : "=r"(r0), "=r"(r1), "=r"(r2), "=r"(r3) : "r"(addr))

#define MMAF16(d, a, b) \
    asm volatile("mma.sync.aligned.m16n8k16.row.col.f32.f16.f16.f32 " \
        "{%0,%1,%2,%3}, {%4,%5,%6,%7}, {%8,%9}, {%0,%1,%2,%3};" \
        : "+f"((d)[0]), "+f"((d)[1]), "+f"((d)[2]), "+f"((d)[3]) \
        : "r"((a)[0]), "r"((a)[1]), "r"((a)[2]), "r"((a)[3]), \
          "r"((b)[0]), "r"((b)[1]))

__global__ void __launch_bounds__(256, 2)
gemm_tc(const __half* __restrict__ Ah, const __half* __restrict__ Bh,
        float* __restrict__ C, int K, int lda, int ldb, int ldc,
        const float* __restrict__ bias, int mode, int nmax)
{
    extern __shared__ char smem[];
    const uint32_t sb = smem_u32(smem);
    const int tid = threadIdx.x;
    const int wid = tid >> 5;
    const int lid = tid & 31;
    const int warp_m = wid & 3;
    const int warp_n = wid >> 2;
    const int m0 = blockIdx.y * TCM;
    const int n0 = blockIdx.x * TCN;
    const int kz = gridDim.z;
    const int KT = K / TCK / kz;
    const int kt0 = blockIdx.z * KT;

    const __half* planes[2] = {Ah, Bh};
    const int plds[2] = {lda, ldb};
    const int pbase[2] = {m0, n0};

    auto issue_tile = [&](int j) {
        if (j < KT) {
            int kofs = (kt0 + j) * TCK;
            uint32_t dbase = sb + (j % NSTAGE) * BUF_B;
            #pragma unroll
            for (int t = 0; t < 8; t++) {
                int idx = t * 256 + tid;
                int p = idx >> 10;
                int rem = idx & 1023;
                int row = rem >> 3;
                int c = rem & 7;
                const __half* src = planes[p]
                    + (size_t)(pbase[p] + row) * plds[p] + kofs + c * 8;
                uint32_t dst = dbase + p * TILE_B + SW128((uint32_t)row * 128 + c * 16);
                asm volatile("cp.async.cg.shared.global [%0], [%1], 16;"
                             :: "r"(dst), "l"(src) : "memory");
            }
        }
        asm volatile("cp.async.commit_group;" ::: "memory");
    };

    float acc[2][8][4];
    #pragma unroll
    for (int i = 0; i < 2; i++)
        #pragma unroll
        for (int j = 0; j < 8; j++)
            #pragma unroll
            for (int q = 0; q < 4; q++) acc[i][j][q] = 0.f;

    issue_tile(0);
    issue_tile(1);

    const int a_r = (lid & 7) + ((lid & 8) ? 8 : 0);
    const int a_kh = (lid & 16) ? 8 : 0;
    const int b_r = (lid & 7) + ((lid & 16) ? 8 : 0);
    const int b_kh = (lid & 8) ? 8 : 0;

    for (int kt = 0; kt < KT; kt++) {
        asm volatile("cp.async.wait_group 1;" ::: "memory");
        __syncthreads();
        issue_tile(kt + 2);

        uint32_t buf = sb + (kt % NSTAGE) * BUF_B;
        #pragma unroll
        for (int k16 = 0; k16 < 4; k16++) {
            uint32_t af[2][4];
            uint32_t bf[8][2];
            #pragma unroll
            for (int im = 0; im < 2; im++) {
                int row = warp_m * 32 + im * 16 + a_r;
                int kb = (k16 * 16 + a_kh) * 2;
                uint32_t ad = buf + SW128((uint32_t)row * 128 + kb);
                LDMX4(af[im][0], af[im][1], af[im][2], af[im][3], ad);
            }
            #pragma unroll
            for (int g = 0; g < 4; g++) {
                int row = warp_n * 64 + g * 16 + b_r;
                int kb = (k16 * 16 + b_kh) * 2;
                uint32_t bd = buf + TILE_B + SW128((uint32_t)row * 128 + kb);
                LDMX4(bf[g*2][0], bf[g*2][1], bf[g*2+1][0], bf[g*2+1][1], bd);
            }
            #pragma unroll
            for (int im = 0; im < 2; im++) {
                #pragma unroll
                for (int in = 0; in < 8; in++) {
                    MMAF16(acc[im][in], af[im], bf[in]);
                }
            }
        }
    }

    const int rbase = m0 + warp_m * 32 + (lid >> 2);
    const int cbase = n0 + warp_n * 64 + (lid & 3) * 2;
    #pragma unroll
    for (int im = 0; im < 2; im++) {
        #pragma unroll
        for (int in = 0; in < 8; in++) {
            int c = cbase + in * 8;
            if (c >= nmax) continue;
            float v0 = acc[im][in][0], v1 = acc[im][in][1];
            float v2 = acc[im][in][2], v3 = acc[im][in][3];
            if (mode == 1) {
                float b0 = bias[c], b1 = bias[c + 1];
                v0 += b0; v1 += b1; v2 += b0; v3 += b1;
                v0 = (v0 > 20.f) ? v0 : log1pf(expf(v0));
                v1 = (v1 > 20.f) ? v1 : log1pf(expf(v1));
                v2 = (v2 > 20.f) ? v2 : log1pf(expf(v2));
                v3 = (v3 > 20.f) ? v3 : log1pf(expf(v3));
            }
            int r0 = rbase + im * 16;
            if (kz > 1) {
                atomicAdd(&C[(size_t)r0 * ldc + c],           v0);
                atomicAdd(&C[(size_t)r0 * ldc + c + 1],       v1);
                atomicAdd(&C[(size_t)(r0 + 8) * ldc + c],     v2);
                atomicAdd(&C[(size_t)(r0 + 8) * ldc + c + 1], v3);
            } else {
                *(float2*)(C + (size_t)r0 * ldc + c)       = make_float2(v0, v1);
                *(float2*)(C + (size_t)(r0 + 8) * ldc + c) = make_float2(v2, v3);
            }
        }
    }
}

// ---------------------------------------------------------------------------
// Causal depthwise conv (K=4) + bias + SiLU -> x fp32 + x fp16 (scalar).
// ---------------------------------------------------------------------------
__global__ void conv_silu_kernel(const float* __restrict__ proj,
                                 const float* __restrict__ conv_w,
                                 const float* __restrict__ conv_b,
                                 float* __restrict__ xout,
                                 __half* __restrict__ xh)
{
    size_t idx = (size_t)blockIdx.x * blockDim.x + threadIdx.x;
    if (idx >= (size_t)Mq * Dq) return;
    int d = (int)(idx % Dq);
    int l = (int)((idx / Dq) % Lq);
    int b = (int)(idx / ((size_t)Dq * Lq));

    const float* pb = proj + (size_t)b * Lq * E2D + d;
    float acc = conv_b[d];
    #pragma unroll
    for (int k = 0; k < Kq; k++) {
        int li = l - (Kq - 1) + k;
        if (li >= 0)
            acc = fmaf(pb[(size_t)li * E2D], conv_w[d * Kq + k], acc);
    }
    float xv = acc / (1.f + __expf(-acc));
    xout[idx] = xv;
    xh[idx] = __float2half_rn(xv);
}

// ---------------------------------------------------------------------------
// Chunked SSM scan (two-pass, exact by linearity). NC=8 chunks of 128.
// pass2 inlines the prefix combine (<=7 cheap extra loads per thread).
// ---------------------------------------------------------------------------
__device__ __forceinline__ void scan_negA(const float* A_log, int d, int nbase,
                                          float& a0, float& a1, float& a2, float& a3,
                                          bool& fast)
{
    a0 = -__expf(A_log[d * Nq + nbase + 0]);
    a1 = -__expf(A_log[d * Nq + nbase + 1]);
    a2 = -__expf(A_log[d * Nq + nbase + 2]);
    a3 = -__expf(A_log[d * Nq + nbase + 3]);
    fast = (fabsf(a0 + (float)(nbase + 1)) < 1e-3f * (nbase + 1))
        && (fabsf(a1 + (float)(nbase + 2)) < 1e-3f * (nbase + 2))
        && (fabsf(a2 + (float)(nbase + 3)) < 1e-3f * (nbase + 3))
        && (fabsf(a3 + (float)(nbase + 4)) < 1e-3f * (nbase + 4));
}

__global__ void __launch_bounds__(128)
scan_pass1(const float* __restrict__ ssm,
           const float* __restrict__ dt,
           const float* __restrict__ x,
           const float* __restrict__ A_log,
           float* __restrict__ hend,
           float* __restrict__ Ssum)
{
    const int quarter = threadIdx.x & 3;
    const int dl = threadIdx.x >> 2;
    const int d = blockIdx.x * 32 + dl;
    const int b = blockIdx.y;
    const int c = blockIdx.z;
    const int nbase = quarter * 4;
    const int l0 = c * CL;

    float negA0, negA1, negA2, negA3; bool fast;
    scan_negA(A_log, d, nbase, negA0, negA1, negA2, negA3, fast);

    const float* ssm_b = ssm + (size_t)b * Lq * SSMW;
    const float* dt_b  = dt  + (size_t)b * Lq * Dq + d;
    const float* x_b   = x   + (size_t)b * Lq * Dq + d;

    float h0 = 0.f, h1 = 0.f, h2 = 0.f, h3 = 0.f;
    float S = 0.f;

    float pdt[2], px[2];
    float4 pB[2];
    #pragma unroll
    for (int s = 0; s < 2; s++) {
        pdt[s] = dt_b[(size_t)(l0 + s) * Dq];
        px[s]  = x_b[(size_t)(l0 + s) * Dq];
        pB[s]  = *(const float4*)(ssm_b + (size_t)(l0 + s) * SSMW + Rq + nbase);
    }

    for (int i = 0; i < CL; i++) {
        const int s = i & 1;
        float cdt = pdt[s], cx = px[s];
        float4 cB = pB[s];
        if (i + 2 < CL) {
            pdt[s] = dt_b[(size_t)(l0 + i + 2) * Dq];
            px[s]  = x_b[(size_t)(l0 + i + 2) * Dq];
            pB[s]  = *(const float4*)(ssm_b + (size_t)(l0 + i + 2) * SSMW + Rq + nbase);
        }

        float r0, r1, r2, r3;
        if (fast) {
            float q = __expf(-cdt);
            float q2 = q * q;
            float q4 = q2 * q2;
            r0 = q;
            if (quarter & 1) r0 *= q4;
            if (quarter & 2) r0 *= q4 * q4;
            r1 = r0 * q; r2 = r1 * q; r3 = r2 * q;
        } else {
            r0 = __expf(cdt * negA0);
            r1 = __expf(cdt * negA1);
            r2 = __expf(cdt * negA2);
            r3 = __expf(cdt * negA3);
        }

        S += cdt;
        float k = cdt * cx;
        h0 = fmaf(r0, h0, k * cB.x);
        h1 = fmaf(r1, h1, k * cB.y);
        h2 = fmaf(r2, h2, k * cB.z);
        h3 = fmaf(r3, h3, k * cB.w);
    }

    size_t hidx = ((((size_t)b * NC + c) * Dq) + d) * Nq + nbase;
    *(float4*)(hend + hidx) = make_float4(h0, h1, h2, h3);
    if (quarter == 0)
        Ssum[((size_t)b * NC + c) * Dq + d] = S;
}

__global__ void __launch_bounds__(128)
scan_pass2(const float* __restrict__ ssm,
           const float* __restrict__ dt,
           const float* __restrict__ x,
           const float* __restrict__ proj,
           const float* __restrict__ A_log,
           const float* __restrict__ D_param,
           const float* __restrict__ hend,
           const float* __restrict__ Ssum,
           __half* __restrict__ yh)
{
    const int quarter = threadIdx.x & 3;
    const int dl = threadIdx.x >> 2;
    const int d = blockIdx.x * 32 + dl;
    const int b = blockIdx.y;
    const int c = blockIdx.z;
    const int nbase = quarter * 4;
    const int l0 = c * CL;

    float negA0, negA1, negA2, negA3; bool fast;
    scan_negA(A_log, d, nbase, negA0, negA1, negA2, negA3, fast);
    const float Dp = D_param[d];

    // inline prefix combine: h_in(c) via diagonal propagation over j < c
    float h0 = 0.f, h1 = 0.f, h2 = 0.f, h3 = 0.f;
    {
        size_t base = (((size_t)b * NC) * Dq + d) * Nq + nbase;
        size_t stride = (size_t)Dq * Nq;
        for (int j = 0; j < c; j++) {
            float S = Ssum[((size_t)b * NC + j) * Dq + d];
            float4 he = *(const float4*)(hend + base + (size_t)j * stride);
            float p0 = __expf(negA0 * S);
            float p1 = __expf(negA1 * S);
            float p2 = __expf(negA2 * S);
            float p3 = __expf(negA3 * S);
            h0 = fmaf(p0, h0, he.x);
            h1 = fmaf(p1, h1, he.y);
            h2 = fmaf(p2, h2, he.z);
            h3 = fmaf(p3, h3, he.w);
        }
    }

    const float* ssm_b  = ssm  + (size_t)b * Lq * SSMW;
    const float* dt_b   = dt   + (size_t)b * Lq * Dq + d;
    const float* x_b    = x    + (size_t)b * Lq * Dq + d;
    const float* g_bp   = proj + (size_t)b * Lq * E2D + Dq + d;
    __half* yh_b = yh + (size_t)b * Lq * Dq + d;

    float pdt[2], px[2], pg[2];
    float4 pB[2], pC[2];
    #pragma unroll
    for (int s = 0; s < 2; s++) {
        pdt[s] = dt_b[(size_t)(l0 + s) * Dq];
        px[s]  = x_b[(size_t)(l0 + s) * Dq];
        pg[s]  = g_bp[(size_t)(l0 + s) * E2D];
        pB[s]  = *(const float4*)(ssm_b + (size_t)(l0 + s) * SSMW + Rq + nbase);
        pC[s]  = *(const float4*)(ssm_b + (size_t)(l0 + s) * SSMW + Rq + Nq + nbase);
    }

    for (int i = 0; i < CL; i++) {
        const int s = i & 1;
        float cdt = pdt[s], cx = px[s], cg = pg[s];
        float4 cB = pB[s], cC = pC[s];
        if (i + 2 < CL) {
            pdt[s] = dt_b[(size_t)(l0 + i + 2) * Dq];
            px[s]  = x_b[(size_t)(l0 + i + 2) * Dq];
            pg[s]  = g_bp[(size_t)(l0 + i + 2) * E2D];
            pB[s]  = *(const float4*)(ssm_b + (size_t)(l0 + i + 2) * SSMW + Rq + nbase);
            pC[s]  = *(const float4*)(ssm_b + (size_t)(l0 + i + 2) * SSMW + Rq + Nq + nbase);
        }

        float r0, r1, r2, r3;
        if (fast) {
            float q = __expf(-cdt);
            float q2 = q * q;
            float q4 = q2 * q2;
            r0 = q;
            if (quarter & 1) r0 *= q4;
            if (quarter & 2) r0 *= q4 * q4;
            r1 = r0 * q; r2 = r1 * q; r3 = r2 * q;
        } else {
            r0 = __expf(cdt * negA0);
            r1 = __expf(cdt * negA1);
            r2 = __expf(cdt * negA2);
            r3 = __expf(cdt * negA3);
        }

        float k = cdt * cx;
        h0 = fmaf(r0, h0, k * cB.x);
        h1 = fmaf(r1, h1, k * cB.y);
        h2 = fmaf(r2, h2, k * cB.z);
        h3 = fmaf(r3, h3, k * cB.w);

        float cacc = fmaf(h0, cC.x, fmaf(h1, cC.y, fmaf(h2, cC.z, h3 * cC.w)));
        cacc += __shfl_xor_sync(0xffffffffu, cacc, 1, 4);
        cacc += __shfl_xor_sync(0xffffffffu, cacc, 2, 4);

        if (quarter == 0) {
            float sg = cg / (1.f + __expf(-cg));
            float yv = (cacc + cx * Dp) * sg;
            yh_b[(size_t)(l0 + i) * Dq] = __float2half_rn(yv);
        }
    }
}

// ---------------------------------------------------------------------------
extern "C" void kernel_launch(void* const* d_in, const int* in_sizes, int n_in,
                              void* d_out, int out_size)
{
    const float* hidden = (const float*)d_in[0];
    const float* W_in   = (const float*)d_in[1];
    const float* conv_w = (const float*)d_in[2];
    const float* conv_b = (const float*)d_in[3];
    const float* W_x    = (const float*)d_in[4];
    const float* W_dt   = (const float*)d_in[5];
    const float* b_dt   = (const float*)d_in[6];
    const float* A_log  = (const float*)d_in[7];
    const float* Dparam = (const float*)d_in[8];
    const float* W_out  = (const float*)d_in[9];
    float* out = (float*)d_out;

    float *proj, *xbuf, *ssm, *dtbuf, *hend, *Ssum;
    cudaGetSymbolAddress((void**)&proj, g_proj);
    cudaGetSymbolAddress((void**)&xbuf, g_x);
    cudaGetSymbolAddress((void**)&ssm, g_ssm);
    cudaGetSymbolAddress((void**)&dtbuf, g_dt);
    cudaGetSymbolAddress((void**)&hend, g_hend);
    cudaGetSymbolAddress((void**)&Ssum, g_S);

    __half *hidh, *winh, *xh, *wxh, *dtlrh, *wdth, *yh, *wouth;
    cudaGetSymbolAddress((void**)&hidh, g_hid_h);
    cudaGetSymbolAddress((void**)&winh, g_win_h);
    cudaGetSymbolAddress((void**)&xh, g_x_h);
    cudaGetSymbolAddress((void**)&wxh, g_wx_h);
    cudaGetSymbolAddress((void**)&dtlrh, g_dtlr_h);
    cudaGetSymbolAddress((void**)&wdth, g_wdt_h);
    cudaGetSymbolAddress((void**)&yh, g_y_h);
    cudaGetSymbolAddress((void**)&wouth, g_wout_h);

    cudaFuncSetAttribute(gemm_tc, cudaFuncAttributeMaxDynamicSharedMemorySize,
                         SMEM_TC_TOTAL);

    auto nblk = [](size_t n) { return (unsigned)((n + 255) / 256); };

    // launch 0: hidden -> fp16
    cvt_f16<<<nblk((size_t)Mq * Hq / 4), 256>>>(hidden, hidh, Mq, Hq, Hq);
    // launch 1: all weight conversions fused
    prep_weights<<<nblk(PW_TOT), 256>>>(W_in, winh, W_dt, wdth, W_x, wxh,
                                        W_out, wouth);
    // launch 2: zero atomic-accumulated outputs (ssm, d_out)
    zeros_kernel<<<nblk(Z_N1 + Z_N2), 256>>>(ssm, out);

    // launch 3 (profiled): proj = hidden @ W_in^T : (2048, 4096), K=1024
    {
        dim3 grid(E2D / TCN, Mq / TCM, 1);
        gemm_tc<<<grid, 256, SMEM_TC_TOTAL>>>(hidh, winh, proj,
                                              Hq, Hq, Hq, E2D, nullptr, 0, E2D);
    }

    // conv + silu -> x (fp32) and x (fp16)
    conv_silu_kernel<<<nblk((size_t)Mq * Dq), 256>>>(proj, conv_w, conv_b,
                                                     xbuf, xh);

    // ssm_p = x @ W_x^T : (2048, 96), tensor cores, split-K=4 atomic
    {
        dim3 grid(1, Mq / TCM, 4);   // KT = 2048/64/4 = 8
        gemm_tc<<<grid, 256, SMEM_TC_TOTAL>>>(xh, wxh, ssm,
                                              Dq, Dq, Dq, SSMW, nullptr, 0, SSMW);
    }

    // dt = softplus(dt_lr @ W_dt^T + b_dt) : (2048, 2048), K=64 (KT=1)
    cvt_f16<<<nblk((size_t)Mq * Rq / 4), 256>>>(ssm, dtlrh, Mq, SSMW, Rq);
    {
        dim3 grid(Dq / TCN, Mq / TCM, 1);
        gemm_tc<<<grid, 256, SMEM_TC_TOTAL>>>(dtlrh, wdth, dtbuf,
                                              Rq, Rq, Rq, Dq, b_dt, 1, Dq);
    }

    // chunked scan: pass1 -> pass2 (combine inlined; y written as fp16)
    {
        dim3 g1(Dq / 32, Bq, NC);
        scan_pass1<<<g1, 128>>>(ssm, dtbuf, xbuf, A_log, hend, Ssum);
        scan_pass2<<<g1, 128>>>(ssm, dtbuf, xbuf, proj, A_log, Dparam,
                                hend, Ssum, yh);
    }

    // out = y @ W_out^T : (2048, 1024), K=2048, split-K=2 atomic into d_out
    {
        dim3 grid(Hq / TCN, Mq / TCM, 2);   // KT = 16
        gemm_tc<<<grid, 256, SMEM_TC_TOTAL>>>(yh, wouth, out,
                                              Dq, Dq, Dq, Hq, nullptr, 0, Hq);
    }
}